// round 1
// baseline (speedup 1.0000x reference)
#include <cuda_runtime.h>
#include <math.h>

// ---------------------------------------------------------------------------
// Involution CNN forward, fp32 baseline.
// Layers: (200->64,k2,s2,p0) (64->128,k2,s2,p0) (128->256,k3,s1,p1) + FC 4096->16
// B=1024, input 16x16.
// ---------------------------------------------------------------------------

#define BATCH 1024

// Scratch buffers (device globals; no runtime allocation allowed).
__device__ float g_xi  [1024 * 64 * 256];   // largest xi (layer1); reused L2/L3
__device__ float g_xp  [1024 * 200 * 64];   // pooled input (layer1 largest)
__device__ float g_r   [1024 * 64 * 64];    // reduce-branch output (4.19M floats, max)
__device__ float g_kern[1024 * 4 * 64];     // dynamic kernels (262144 floats, max)
__device__ float g_out1[1024 * 64 * 64];
__device__ float g_out2[1024 * 128 * 16];
__device__ float g_out3[1024 * 256 * 16];
__device__ float g_scale[256];
__device__ float g_shift[256];

// ---------------------------------------------------------------------------
// Pixel-wise GEMM: OUT[b,o,p] = sum_c W[o,c] * X[b,c,p]
// Pixel dim flattened over g = b*HW + p (tiles may span batches when HW<64).
// Tile: 64 o x 64 px, 256 threads, 4x4 microtile, TC=16 k-slab.
// Requires: O % 64 == 0, (B*HW) % 64 == 0, HW % 4 == 0, C % 4 == 0.
// ---------------------------------------------------------------------------
__global__ __launch_bounds__(256) void gemm_pixel(
    const float* __restrict__ W, const float* __restrict__ X,
    float* __restrict__ OUT, int O, int C, int HW) {
  __shared__ float Ws[16][68];   // [c][o], padded row to dodge bank conflicts
  __shared__ float Xs[16][64];   // [c][p]

  const int g0 = blockIdx.x * 64;
  const int o0 = blockIdx.y * 64;
  const int t  = threadIdx.x;
  const int tx = t & 15;         // pixel group
  const int ty = t >> 4;         // o group
  const int lw_o = t >> 2;               // 0..63
  const int lw_c = (t & 3) << 2;         // 0,4,8,12
  const int lx_c = t >> 4;               // 0..15
  const int lx_p = (t & 15) << 2;        // 0..60

  // X source (batch/pixel constant over the k loop)
  const int gx = g0 + lx_p;
  const int bx = gx / HW;
  const int px = gx - bx * HW;
  const float* Xbase = X + ((size_t)bx * C) * HW + px;
  const float* Wrow  = W + (size_t)(o0 + lw_o) * C;

  float acc[4][4] = {};

  for (int c0 = 0; c0 < C; c0 += 16) {
    // --- load W tile (transposed into smem) ---
    float4 wv = make_float4(0.f, 0.f, 0.f, 0.f);
    const int wc = c0 + lw_c;
    if (wc + 3 < C) {
      wv = *(const float4*)(Wrow + wc);
    } else {
      if (wc + 0 < C) wv.x = Wrow[wc + 0];
      if (wc + 1 < C) wv.y = Wrow[wc + 1];
      if (wc + 2 < C) wv.z = Wrow[wc + 2];
      if (wc + 3 < C) wv.w = Wrow[wc + 3];
    }
    Ws[lw_c + 0][lw_o] = wv.x;
    Ws[lw_c + 1][lw_o] = wv.y;
    Ws[lw_c + 2][lw_o] = wv.z;
    Ws[lw_c + 3][lw_o] = wv.w;

    // --- load X tile ---
    float4 xv = make_float4(0.f, 0.f, 0.f, 0.f);
    const int xc = c0 + lx_c;
    if (xc < C) xv = *(const float4*)(Xbase + (size_t)xc * HW);
    *(float4*)&Xs[lx_c][lx_p] = xv;

    __syncthreads();

#pragma unroll
    for (int cc = 0; cc < 16; cc++) {
      const float4 a  = *(const float4*)&Ws[cc][ty << 2];
      const float4 x4 = *(const float4*)&Xs[cc][tx << 2];
      acc[0][0] = fmaf(a.x, x4.x, acc[0][0]);
      acc[0][1] = fmaf(a.x, x4.y, acc[0][1]);
      acc[0][2] = fmaf(a.x, x4.z, acc[0][2]);
      acc[0][3] = fmaf(a.x, x4.w, acc[0][3]);
      acc[1][0] = fmaf(a.y, x4.x, acc[1][0]);
      acc[1][1] = fmaf(a.y, x4.y, acc[1][1]);
      acc[1][2] = fmaf(a.y, x4.z, acc[1][2]);
      acc[1][3] = fmaf(a.y, x4.w, acc[1][3]);
      acc[2][0] = fmaf(a.z, x4.x, acc[2][0]);
      acc[2][1] = fmaf(a.z, x4.y, acc[2][1]);
      acc[2][2] = fmaf(a.z, x4.z, acc[2][2]);
      acc[2][3] = fmaf(a.z, x4.w, acc[2][3]);
      acc[3][0] = fmaf(a.w, x4.x, acc[3][0]);
      acc[3][1] = fmaf(a.w, x4.y, acc[3][1]);
      acc[3][2] = fmaf(a.w, x4.z, acc[3][2]);
      acc[3][3] = fmaf(a.w, x4.w, acc[3][3]);
    }
    __syncthreads();
  }

  // --- write 4x4 microtile ---
  const int go = g0 + (tx << 2);
  const int bo = go / HW;
  const int po = go - bo * HW;
  float* Obase = OUT + ((size_t)bo * O + o0 + (ty << 2)) * HW + po;
#pragma unroll
  for (int i = 0; i < 4; i++) {
    float4 v = make_float4(acc[i][0], acc[i][1], acc[i][2], acc[i][3]);
    *(float4*)(Obase + (size_t)i * HW) = v;
  }
}

// ---------------------------------------------------------------------------
// 2x2 average pool (stride 2). xp layout [B,C,Ho,Wo], linear index == output.
// ---------------------------------------------------------------------------
__global__ __launch_bounds__(256) void pool2_kernel(
    const float* __restrict__ x, float* __restrict__ xp,
    int Hi, int Wi, int total) {
  const int idx = blockIdx.x * 256 + threadIdx.x;
  if (idx >= total) return;
  const int Wo = Wi >> 1, Ho = Hi >> 1;
  const int wo = idx % Wo;
  int tmp = idx / Wo;
  const int ho = tmp % Ho;
  const int bc = tmp / Ho;   // combined b*C + c
  const float* p = x + ((size_t)bc * Hi + 2 * ho) * Wi + 2 * wo;
  xp[idx] = 0.25f * (p[0] + p[1] + p[Wi] + p[Wi + 1]);
}

// ---------------------------------------------------------------------------
// BatchNorm stats over (B, H, W) per channel -> folded scale/shift.
// One CTA per channel.
// ---------------------------------------------------------------------------
__global__ __launch_bounds__(256) void bn_stats(
    const float* __restrict__ r, const float* __restrict__ gamma,
    const float* __restrict__ beta, float* __restrict__ scale,
    float* __restrict__ shift, int O, int HW) {
  const int o = blockIdx.x;
  const int N = BATCH * HW;
  float s = 0.f, s2 = 0.f;
  for (int g = threadIdx.x; g < N; g += 256) {
    const int b = g / HW;
    const int p = g - b * HW;
    const float v = r[((size_t)b * O + o) * HW + p];
    s += v;
    s2 = fmaf(v, v, s2);
  }
  __shared__ float ss[256], ss2[256];
  ss[threadIdx.x] = s;
  ss2[threadIdx.x] = s2;
  __syncthreads();
  for (int d = 128; d > 0; d >>= 1) {
    if (threadIdx.x < d) {
      ss[threadIdx.x]  += ss[threadIdx.x + d];
      ss2[threadIdx.x] += ss2[threadIdx.x + d];
    }
    __syncthreads();
  }
  if (threadIdx.x == 0) {
    const float inv_n = 1.f / (float)N;
    const float mean = ss[0] * inv_n;
    const float var  = ss2[0] * inv_n - mean * mean;
    const float sc   = gamma[o] * rsqrtf(var + 1e-5f);
    scale[o] = sc;
    shift[o] = beta[o] - mean * sc;
  }
}

// ---------------------------------------------------------------------------
// Span GEMM with fused BN+ReLU: kern[b,kk,p] = sum_o Wspan[kk,o]*relu(sc*r+sh)
// Each thread handles 2 consecutive pixels.
// ---------------------------------------------------------------------------
template <int KK>
__global__ __launch_bounds__(256) void span_kernel(
    const float* __restrict__ Wspan, const float* __restrict__ r,
    const float* __restrict__ scale, const float* __restrict__ shift,
    float* __restrict__ kern, int O, int HW, int G) {
  __shared__ float Ws[KK * 256];
  __shared__ float sc[256], sh[256];
  for (int i = threadIdx.x; i < KK * O; i += 256) Ws[i] = Wspan[i];
  for (int i = threadIdx.x; i < O; i += 256) { sc[i] = scale[i]; sh[i] = shift[i]; }
  __syncthreads();

  const int g0 = (blockIdx.x * 256 + threadIdx.x) * 2;
  if (g0 >= G) return;
  const int b = g0 / HW;
  const int p = g0 - b * HW;
  const float* rb = r + ((size_t)b * O) * HW + p;

  float a0[KK] = {};
  float a1[KK] = {};
  for (int o = 0; o < O; o++) {
    float v0 = rb[(size_t)o * HW];
    float v1 = rb[(size_t)o * HW + 1];
    const float s_ = sc[o], t_ = sh[o];
    v0 = fmaxf(fmaf(v0, s_, t_), 0.f);
    v1 = fmaxf(fmaf(v1, s_, t_), 0.f);
#pragma unroll
    for (int kk = 0; kk < KK; kk++) {
      const float w = Ws[kk * O + o];
      a0[kk] = fmaf(w, v0, a0[kk]);
      a1[kk] = fmaf(w, v1, a1[kk]);
    }
  }
  float* kb = kern + (size_t)b * KK * HW + p;
#pragma unroll
  for (int kk = 0; kk < KK; kk++) {
    kb[(size_t)kk * HW]     = a0[kk];
    kb[(size_t)kk * HW + 1] = a1[kk];
  }
}

// ---------------------------------------------------------------------------
// Apply dynamic kernel to unfolded patches:
// out[b,o,ho,wo] = sum_{kh,kw} kern[b,kh*K+kw,ho,wo] * xi[b,o,ho*S+kh-PAD,wo*S+kw-PAD]
// ---------------------------------------------------------------------------
template <int K, int S, int PAD>
__global__ __launch_bounds__(256) void apply_kernel(
    const float* __restrict__ kern, const float* __restrict__ xi,
    float* __restrict__ out, int O, int Hi, int Wi, int Ho, int Wo, int total) {
  const int idx = blockIdx.x * 256 + threadIdx.x;
  if (idx >= total) return;
  const int HWo = Ho * Wo;
  const int q  = idx % HWo;
  const int bo = idx / HWo;
  const int o  = bo % O;
  const int b  = bo / O;
  const int ho = q / Wo;
  const int wo = q - ho * Wo;

  const float* kb = kern + (size_t)b * (K * K) * HWo + q;
  const float* xb = xi + ((size_t)b * O + o) * Hi * Wi;

  float acc = 0.f;
#pragma unroll
  for (int kh = 0; kh < K; kh++) {
    const int hi = ho * S + kh - PAD;
    if (hi < 0 || hi >= Hi) continue;
#pragma unroll
    for (int kw = 0; kw < K; kw++) {
      const int wi = wo * S + kw - PAD;
      if (wi < 0 || wi >= Wi) continue;
      acc = fmaf(kb[(size_t)(kh * K + kw) * HWo], xb[hi * Wi + wi], acc);
    }
  }
  out[idx] = acc;
}

// ---------------------------------------------------------------------------
// FC: out[b,n] = sum_f h[b,f]*Wfc[n,f] + bfc[n]   (F=4096, N=16)
// One thread per output, float4 dots. 16 n-threads per b share h via L1.
// ---------------------------------------------------------------------------
__global__ __launch_bounds__(256) void fc_kernel(
    const float* __restrict__ h, const float* __restrict__ Wfc,
    const float* __restrict__ bfc, float* __restrict__ out) {
  const int t = blockIdx.x * 256 + threadIdx.x;   // 16384 threads
  const int n = t & 15;
  const int b = t >> 4;
  const float4* hp = (const float4*)(h + (size_t)b * 4096);
  const float4* wp = (const float4*)(Wfc + (size_t)n * 4096);
  float acc = 0.f;
#pragma unroll 4
  for (int f = 0; f < 1024; f++) {
    const float4 hv = hp[f];
    const float4 wv = wp[f];
    acc = fmaf(hv.x, wv.x, acc);
    acc = fmaf(hv.y, wv.y, acc);
    acc = fmaf(hv.z, wv.z, acc);
    acc = fmaf(hv.w, wv.w, acc);
  }
  out[t] = acc + bfc[n];
}

// ---------------------------------------------------------------------------
// Host launcher
// ---------------------------------------------------------------------------
extern "C" void kernel_launch(void* const* d_in, const int* in_sizes, int n_in,
                              void* d_out, int out_size) {
  const float* x   = (const float*)d_in[0];
  const float* Wi1 = (const float*)d_in[1];
  const float* Wr1 = (const float*)d_in[2];
  const float* ga1 = (const float*)d_in[3];
  const float* be1 = (const float*)d_in[4];
  const float* Wsp1 = (const float*)d_in[5];
  const float* Wi2 = (const float*)d_in[6];
  const float* Wr2 = (const float*)d_in[7];
  const float* ga2 = (const float*)d_in[8];
  const float* be2 = (const float*)d_in[9];
  const float* Wsp2 = (const float*)d_in[10];
  const float* Wi3 = (const float*)d_in[11];
  const float* Wr3 = (const float*)d_in[12];
  const float* ga3 = (const float*)d_in[13];
  const float* be3 = (const float*)d_in[14];
  const float* Wsp3 = (const float*)d_in[15];
  const float* Wfc = (const float*)d_in[16];
  const float* bfc = (const float*)d_in[17];
  float* out = (float*)d_out;

  float *xi, *xp, *r, *kern, *o1, *o2, *o3, *scale, *shift;
  cudaGetSymbolAddress((void**)&xi,    g_xi);
  cudaGetSymbolAddress((void**)&xp,    g_xp);
  cudaGetSymbolAddress((void**)&r,     g_r);
  cudaGetSymbolAddress((void**)&kern,  g_kern);
  cudaGetSymbolAddress((void**)&o1,    g_out1);
  cudaGetSymbolAddress((void**)&o2,    g_out2);
  cudaGetSymbolAddress((void**)&o3,    g_out3);
  cudaGetSymbolAddress((void**)&scale, g_scale);
  cudaGetSymbolAddress((void**)&shift, g_shift);

  // ---------------- Layer 1: 200 -> 64, k=2, s=2, p=0, 16x16 -> 8x8 ----------
  gemm_pixel<<<dim3(4096, 1), 256>>>(Wi1, x, xi, 64, 200, 256);          // xi1 [B,64,256]
  pool2_kernel<<<(1024 * 200 * 64 + 255) / 256, 256>>>(x, xp, 16, 16,
                                                       1024 * 200 * 64); // xp [B,200,64]
  gemm_pixel<<<dim3(1024, 1), 256>>>(Wr1, xp, r, 64, 200, 64);           // r1 [B,64,64]
  bn_stats<<<64, 256>>>(r, ga1, be1, scale, shift, 64, 64);
  span_kernel<4><<<128, 256>>>(Wsp1, r, scale, shift, kern, 64, 64, 65536);
  apply_kernel<2, 2, 0><<<(4194304 + 255) / 256, 256>>>(kern, xi, o1, 64,
                                                        16, 16, 8, 8, 4194304);

  // ---------------- Layer 2: 64 -> 128, k=2, s=2, p=0, 8x8 -> 4x4 ------------
  gemm_pixel<<<dim3(1024, 2), 256>>>(Wi2, o1, xi, 128, 64, 64);          // xi2 [B,128,64]
  pool2_kernel<<<(1024 * 64 * 16 + 255) / 256, 256>>>(o1, xp, 8, 8,
                                                      1024 * 64 * 16);   // xp [B,64,16]
  gemm_pixel<<<dim3(256, 2), 256>>>(Wr2, xp, r, 128, 64, 16);            // r2 [B,128,16]
  bn_stats<<<128, 256>>>(r, ga2, be2, scale, shift, 128, 16);
  span_kernel<4><<<32, 256>>>(Wsp2, r, scale, shift, kern, 128, 16, 16384);
  apply_kernel<2, 2, 0><<<(2097152 + 255) / 256, 256>>>(kern, xi, o2, 128,
                                                        8, 8, 4, 4, 2097152);

  // ---------------- Layer 3: 128 -> 256, k=3, s=1, p=1, 4x4 -> 4x4 -----------
  gemm_pixel<<<dim3(256, 4), 256>>>(Wi3, o2, xi, 256, 128, 16);          // xi3 [B,256,16]
  gemm_pixel<<<dim3(256, 4), 256>>>(Wr3, o2, r, 256, 128, 16);           // r3 [B,256,16]
  bn_stats<<<256, 256>>>(r, ga3, be3, scale, shift, 256, 16);
  span_kernel<9><<<32, 256>>>(Wsp3, r, scale, shift, kern, 256, 16, 16384);
  apply_kernel<3, 1, 1><<<(4194304 + 255) / 256, 256>>>(kern, xi, o3, 256,
                                                        4, 4, 4, 4, 4194304);

  // ---------------- FC: [1024,4096] @ [4096,16]^T + bias ---------------------
  fc_kernel<<<64, 256>>>(o3, Wfc, bfc, out);
}

// round 2
// speedup vs baseline: 1.0183x; 1.0183x over previous
#include <cuda_runtime.h>
#include <math.h>

// ---------------------------------------------------------------------------
// Involution CNN forward. Round 2: f32x2 (FFMA2) GEMM, parallel BN reduction,
// vectorized pool/apply.
// Layers: (200->64,k2,s2,p0) (64->128,k2,s2,p0) (128->256,k3,s1,p1) + FC 4096->16
// B=1024, input 16x16.
// ---------------------------------------------------------------------------

#define BATCH 1024
typedef unsigned long long ull;

// Scratch buffers (device globals; no runtime allocation allowed).
__device__ float g_xi  [1024 * 64 * 256];   // largest xi (layer1); reused L2/L3
__device__ float g_xp  [1024 * 200 * 64];   // pooled input (layer1 largest)
__device__ float g_r   [1024 * 64 * 64];    // reduce-branch output
__device__ float g_kern[1024 * 4 * 64];     // dynamic kernels
__device__ float g_out1[1024 * 64 * 64];
__device__ float g_out2[1024 * 128 * 16];
__device__ float g_out3[1024 * 256 * 16];
__device__ float g_scale[256];
__device__ float g_shift[256];
__device__ float2 g_part[256 * 16];         // BN partial sums

__device__ __forceinline__ ull bcast2(float f) {
  ull d;
  asm("mov.b64 %0, {%1, %1};" : "=l"(d) : "f"(f));
  return d;
}
#define FMA2(d, a, b) asm("fma.rn.f32x2 %0, %1, %2, %0;" : "+l"(d) : "l"(a), "l"(b))

// ---------------------------------------------------------------------------
// Pixel-wise GEMM: OUT[b,o,p] = sum_c W[o,c] * X[b,c,p]
// CTA tile: 64 o x 256 px, 256 threads, per-thread 8o x 8px via f32x2.
// Requires O%64==0, G%256==0, HW%16==0, where G = B*HW.
// ---------------------------------------------------------------------------
__global__ __launch_bounds__(256, 2) void gemm_pixel(
    const float* __restrict__ W, const float* __restrict__ X,
    float* __restrict__ OUT, int O, int C, int HW) {
  __shared__ float Ws[16][68];    // [c][o], padded
  __shared__ float Xs[16][256];   // [c][px]

  const int t  = threadIdx.x;
  const int g0 = blockIdx.x * 256;
  const int o0 = blockIdx.y * 64;
  const int o_base = (t >> 5) * 8;   // warp id selects 8 o's (broadcast reads)
  const int p_base = (t & 31) * 8;

  // W loader: thread -> (o = t>>2, 4 c's)
  const int lw_o = t >> 2;
  const int lw_c = (t & 3) * 4;
  const float* Wrow = W + (size_t)(o0 + lw_o) * C;

  // X loader: 4 float4 per thread; float4 id f = t + 256k
  // px (in floats) = (t&63)*4 is identical for all k; local c = (t>>6) + 4k.
  const int xpx = (t & 63) * 4;
  const int xc0 = t >> 6;
  const int gx  = g0 + xpx;
  const int bx  = gx / HW;
  const int px  = gx - bx * HW;
  const float* Xrow = X + ((size_t)bx * C + xc0) * HW + px;

  ull acc[8][4];
#pragma unroll
  for (int i = 0; i < 8; i++)
#pragma unroll
    for (int j = 0; j < 4; j++) acc[i][j] = 0ull;

  for (int c0 = 0; c0 < C; c0 += 16) {
    // --- load W tile (transposed, zero-padded) ---
    float4 wv = make_float4(0.f, 0.f, 0.f, 0.f);
    const int wc = c0 + lw_c;
    if (wc + 3 < C) {
      wv = *(const float4*)(Wrow + wc);
    } else {
      if (wc + 0 < C) wv.x = Wrow[wc + 0];
      if (wc + 1 < C) wv.y = Wrow[wc + 1];
      if (wc + 2 < C) wv.z = Wrow[wc + 2];
    }
    Ws[lw_c + 0][lw_o] = wv.x;
    Ws[lw_c + 1][lw_o] = wv.y;
    Ws[lw_c + 2][lw_o] = wv.z;
    Ws[lw_c + 3][lw_o] = wv.w;

    // --- load X tile (4 float4, coalesced, conflict-free stores) ---
#pragma unroll
    for (int k = 0; k < 4; k++) {
      const int lc = xc0 + 4 * k;
      float4 xv = make_float4(0.f, 0.f, 0.f, 0.f);
      if (c0 + lc < C) xv = *(const float4*)(Xrow + (size_t)(c0 + 4 * k) * HW);
      *(float4*)&Xs[lc][xpx] = xv;
    }
    __syncthreads();

#pragma unroll
    for (int cc = 0; cc < 16; cc++) {
      const float4 a0 = *(const float4*)&Ws[cc][o_base];
      const float4 a1 = *(const float4*)&Ws[cc][o_base + 4];
      const ulonglong2 xlo = *(const ulonglong2*)&Xs[cc][p_base];
      const ulonglong2 xhi = *(const ulonglong2*)&Xs[cc][p_base + 4];
      ull b;
      b = bcast2(a0.x);
      FMA2(acc[0][0], b, xlo.x); FMA2(acc[0][1], b, xlo.y);
      FMA2(acc[0][2], b, xhi.x); FMA2(acc[0][3], b, xhi.y);
      b = bcast2(a0.y);
      FMA2(acc[1][0], b, xlo.x); FMA2(acc[1][1], b, xlo.y);
      FMA2(acc[1][2], b, xhi.x); FMA2(acc[1][3], b, xhi.y);
      b = bcast2(a0.z);
      FMA2(acc[2][0], b, xlo.x); FMA2(acc[2][1], b, xlo.y);
      FMA2(acc[2][2], b, xhi.x); FMA2(acc[2][3], b, xhi.y);
      b = bcast2(a0.w);
      FMA2(acc[3][0], b, xlo.x); FMA2(acc[3][1], b, xlo.y);
      FMA2(acc[3][2], b, xhi.x); FMA2(acc[3][3], b, xhi.y);
      b = bcast2(a1.x);
      FMA2(acc[4][0], b, xlo.x); FMA2(acc[4][1], b, xlo.y);
      FMA2(acc[4][2], b, xhi.x); FMA2(acc[4][3], b, xhi.y);
      b = bcast2(a1.y);
      FMA2(acc[5][0], b, xlo.x); FMA2(acc[5][1], b, xlo.y);
      FMA2(acc[5][2], b, xhi.x); FMA2(acc[5][3], b, xhi.y);
      b = bcast2(a1.z);
      FMA2(acc[6][0], b, xlo.x); FMA2(acc[6][1], b, xlo.y);
      FMA2(acc[6][2], b, xhi.x); FMA2(acc[6][3], b, xhi.y);
      b = bcast2(a1.w);
      FMA2(acc[7][0], b, xlo.x); FMA2(acc[7][1], b, xlo.y);
      FMA2(acc[7][2], b, xhi.x); FMA2(acc[7][3], b, xhi.y);
    }
    __syncthreads();
  }

  // --- epilogue: 8 rows x 8 px (px run stays in one batch: HW%16==0) ---
  const int go = g0 + p_base;
  const int bo = go / HW;
  const int po = go - bo * HW;
#pragma unroll
  for (int i = 0; i < 8; i++) {
    ull* dst = (ull*)(OUT + ((size_t)bo * O + o0 + o_base + i) * HW + po);
    dst[0] = acc[i][0];
    dst[1] = acc[i][1];
    dst[2] = acc[i][2];
    dst[3] = acc[i][3];
  }
}

// ---------------------------------------------------------------------------
// 2x2 avg pool, 2 outputs per thread (float4 reads, float2 write).
// ---------------------------------------------------------------------------
__global__ __launch_bounds__(256) void pool2v(
    const float* __restrict__ x, float* __restrict__ xp,
    int Hi, int Wi, int total2) {
  const int idx = blockIdx.x * 256 + threadIdx.x;
  if (idx >= total2) return;
  const int Wo = Wi >> 1, Ho = Hi >> 1, WP = Wo >> 1;
  const int wp = idx % WP;
  const int t2 = idx / WP;
  const int ho = t2 % Ho;
  const int bc = t2 / Ho;
  const float* p = x + ((size_t)bc * Hi + 2 * ho) * Wi + 4 * wp;
  const float4 r0 = *(const float4*)p;
  const float4 r1 = *(const float4*)(p + Wi);
  float2 o;
  o.x = 0.25f * (r0.x + r0.y + r1.x + r1.y);
  o.y = 0.25f * (r0.z + r0.w + r1.z + r1.w);
  *(float2*)(xp + (size_t)idx * 2) = o;
}

// ---------------------------------------------------------------------------
// BN stage 1: per (channel, batch-slab) partial sums. grid (O, NS).
// ---------------------------------------------------------------------------
__global__ __launch_bounds__(256) void bn_partial(
    const float* __restrict__ r, float2* __restrict__ part,
    int O, int HW, int nbPerSlab) {
  const int o = blockIdx.x, slab = blockIdx.y, NS = gridDim.y;
  const int n = nbPerSlab * HW;
  const float* base = r + ((size_t)slab * nbPerSlab * O + o) * HW;
  float s = 0.f, s2 = 0.f;
  for (int i = threadIdx.x; i < n; i += 256) {
    const int b = i / HW;
    const int p = i - b * HW;
    const float v = base[(size_t)b * O * HW + p];
    s += v;
    s2 = fmaf(v, v, s2);
  }
  __shared__ float ss[256], ss2[256];
  ss[threadIdx.x] = s;
  ss2[threadIdx.x] = s2;
  __syncthreads();
  for (int d = 128; d > 0; d >>= 1) {
    if (threadIdx.x < d) {
      ss[threadIdx.x]  += ss[threadIdx.x + d];
      ss2[threadIdx.x] += ss2[threadIdx.x + d];
    }
    __syncthreads();
  }
  if (threadIdx.x == 0) part[o * NS + slab] = make_float2(ss[0], ss2[0]);
}

// BN stage 2: fold into scale/shift. One small CTA.
__global__ void bn_finalize(
    const float2* __restrict__ part, const float* __restrict__ gamma,
    const float* __restrict__ beta, float* __restrict__ scale,
    float* __restrict__ shift, int O, int NS, float invN) {
  const int o = threadIdx.x;
  if (o >= O) return;
  float s = 0.f, s2 = 0.f;
  for (int i = 0; i < NS; i++) {
    const float2 v = part[o * NS + i];
    s += v.x;
    s2 += v.y;
  }
  const float mean = s * invN;
  const float var  = s2 * invN - mean * mean;
  const float sc   = gamma[o] * rsqrtf(var + 1e-5f);
  scale[o] = sc;
  shift[o] = beta[o] - mean * sc;
}

// ---------------------------------------------------------------------------
// Span GEMM fused with BN+ReLU: kern[b,kk,p] = sum_o Wspan[kk,o]*relu(sc*r+sh)
// ---------------------------------------------------------------------------
template <int KK>
__global__ __launch_bounds__(256) void span_kernel(
    const float* __restrict__ Wspan, const float* __restrict__ r,
    const float* __restrict__ scale, const float* __restrict__ shift,
    float* __restrict__ kern, int O, int HW) {
  __shared__ float Ws[KK * 256];
  __shared__ float sc[256], sh[256];
  for (int i = threadIdx.x; i < KK * O; i += 256) Ws[i] = Wspan[i];
  for (int i = threadIdx.x; i < O; i += 256) { sc[i] = scale[i]; sh[i] = shift[i]; }
  __syncthreads();

  const int g = blockIdx.x * 256 + threadIdx.x;
  const int b = g / HW;
  const int p = g - b * HW;
  const float* rb = r + ((size_t)b * O) * HW + p;

  float a[KK];
#pragma unroll
  for (int kk = 0; kk < KK; kk++) a[kk] = 0.f;
  for (int o = 0; o < O; o++) {
    const float v = fmaxf(fmaf(rb[(size_t)o * HW], sc[o], sh[o]), 0.f);
#pragma unroll
    for (int kk = 0; kk < KK; kk++) a[kk] = fmaf(Ws[kk * O + o], v, a[kk]);
  }
  float* kb = kern + (size_t)b * KK * HW + p;
#pragma unroll
  for (int kk = 0; kk < KK; kk++) kb[(size_t)kk * HW] = a[kk];
}

// ---------------------------------------------------------------------------
// Apply for k=2, s=2, p=0: 2 horizontal outputs per thread, float4 xi reads.
// ---------------------------------------------------------------------------
__global__ __launch_bounds__(256) void apply2(
    const float* __restrict__ kern, const float* __restrict__ xi,
    float* __restrict__ out, int O, int Hi, int Wi, int Ho, int Wo, int total2) {
  const int idx = blockIdx.x * 256 + threadIdx.x;
  if (idx >= total2) return;
  const int WP = Wo >> 1, HWo = Ho * Wo;
  const int wp = idx % WP;
  const int t2 = idx / WP;
  const int ho = t2 % Ho;
  const int bo = t2 / Ho;
  const int o  = bo % O;
  const int b  = bo / O;

  const float* kb = kern + (size_t)b * 4 * HWo + ho * Wo + 2 * wp;
  const float2 k0 = *(const float2*)(kb);
  const float2 k1 = *(const float2*)(kb + HWo);
  const float2 k2 = *(const float2*)(kb + 2 * (size_t)HWo);
  const float2 k3 = *(const float2*)(kb + 3 * (size_t)HWo);

  const float* xb = xi + ((size_t)b * O + o) * Hi * Wi + (2 * ho) * Wi + 4 * wp;
  const float4 r0 = *(const float4*)xb;
  const float4 r1 = *(const float4*)(xb + Wi);

  float2 res;
  res.x = k0.x * r0.x + k1.x * r0.y + k2.x * r1.x + k3.x * r1.y;
  res.y = k0.y * r0.z + k1.y * r0.w + k2.y * r1.z + k3.y * r1.w;
  *(float2*)(out + (size_t)bo * HWo + ho * Wo + 2 * wp) = res;
}

// ---------------------------------------------------------------------------
// Generic apply (used for k=3, s=1, p=1 layer).
// ---------------------------------------------------------------------------
template <int K, int S, int PAD>
__global__ __launch_bounds__(256) void apply_kernel(
    const float* __restrict__ kern, const float* __restrict__ xi,
    float* __restrict__ out, int O, int Hi, int Wi, int Ho, int Wo, int total) {
  const int idx = blockIdx.x * 256 + threadIdx.x;
  if (idx >= total) return;
  const int HWo = Ho * Wo;
  const int q  = idx % HWo;
  const int bo = idx / HWo;
  const int o  = bo % O;
  const int b  = bo / O;
  const int ho = q / Wo;
  const int wo = q - ho * Wo;

  const float* kb = kern + (size_t)b * (K * K) * HWo + q;
  const float* xb = xi + ((size_t)b * O + o) * Hi * Wi;

  float acc = 0.f;
#pragma unroll
  for (int kh = 0; kh < K; kh++) {
    const int hi = ho * S + kh - PAD;
    if (hi < 0 || hi >= Hi) continue;
#pragma unroll
    for (int kw = 0; kw < K; kw++) {
      const int wi = wo * S + kw - PAD;
      if (wi < 0 || wi >= Wi) continue;
      acc = fmaf(kb[(size_t)(kh * K + kw) * HWo], xb[hi * Wi + wi], acc);
    }
  }
  out[idx] = acc;
}

// ---------------------------------------------------------------------------
// FC: out[b,n] = sum_f h[b,f]*Wfc[n,f] + bfc[n]   (F=4096, N=16)
// ---------------------------------------------------------------------------
__global__ __launch_bounds__(256) void fc_kernel(
    const float* __restrict__ h, const float* __restrict__ Wfc,
    const float* __restrict__ bfc, float* __restrict__ out) {
  const int t = blockIdx.x * 256 + threadIdx.x;   // 16384 threads
  const int n = t & 15;
  const int b = t >> 4;
  const float4* hp = (const float4*)(h + (size_t)b * 4096);
  const float4* wp = (const float4*)(Wfc + (size_t)n * 4096);
  float acc = 0.f;
#pragma unroll 4
  for (int f = 0; f < 1024; f++) {
    const float4 hv = hp[f];
    const float4 wv = wp[f];
    acc = fmaf(hv.x, wv.x, acc);
    acc = fmaf(hv.y, wv.y, acc);
    acc = fmaf(hv.z, wv.z, acc);
    acc = fmaf(hv.w, wv.w, acc);
  }
  out[t] = acc + bfc[n];
}

// ---------------------------------------------------------------------------
// Host launcher
// ---------------------------------------------------------------------------
extern "C" void kernel_launch(void* const* d_in, const int* in_sizes, int n_in,
                              void* d_out, int out_size) {
  const float* x    = (const float*)d_in[0];
  const float* Wi1  = (const float*)d_in[1];
  const float* Wr1  = (const float*)d_in[2];
  const float* ga1  = (const float*)d_in[3];
  const float* be1  = (const float*)d_in[4];
  const float* Wsp1 = (const float*)d_in[5];
  const float* Wi2  = (const float*)d_in[6];
  const float* Wr2  = (const float*)d_in[7];
  const float* ga2  = (const float*)d_in[8];
  const float* be2  = (const float*)d_in[9];
  const float* Wsp2 = (const float*)d_in[10];
  const float* Wi3  = (const float*)d_in[11];
  const float* Wr3  = (const float*)d_in[12];
  const float* ga3  = (const float*)d_in[13];
  const float* be3  = (const float*)d_in[14];
  const float* Wsp3 = (const float*)d_in[15];
  const float* Wfc  = (const float*)d_in[16];
  const float* bfc  = (const float*)d_in[17];
  float* out = (float*)d_out;

  float *xi, *xp, *r, *kern, *o1, *o2, *o3, *scale, *shift;
  float2* part;
  cudaGetSymbolAddress((void**)&xi,    g_xi);
  cudaGetSymbolAddress((void**)&xp,    g_xp);
  cudaGetSymbolAddress((void**)&r,     g_r);
  cudaGetSymbolAddress((void**)&kern,  g_kern);
  cudaGetSymbolAddress((void**)&o1,    g_out1);
  cudaGetSymbolAddress((void**)&o2,    g_out2);
  cudaGetSymbolAddress((void**)&o3,    g_out3);
  cudaGetSymbolAddress((void**)&scale, g_scale);
  cudaGetSymbolAddress((void**)&shift, g_shift);
  cudaGetSymbolAddress((void**)&part,  g_part);

  // ---------------- Layer 1: 200 -> 64, k=2, s=2, p=0, 16x16 -> 8x8 ----------
  gemm_pixel<<<dim3(1024, 1), 256>>>(Wi1, x, xi, 64, 200, 256);
  pool2v<<<25600, 256>>>(x, xp, 16, 16, 6553600);                // [B,200,8,8]
  gemm_pixel<<<dim3(256, 1), 256>>>(Wr1, xp, r, 64, 200, 64);
  bn_partial<<<dim3(64, 16), 256>>>(r, part, 64, 64, 64);
  bn_finalize<<<1, 256>>>(part, ga1, be1, scale, shift, 64, 16, 1.f / 65536.f);
  span_kernel<4><<<256, 256>>>(Wsp1, r, scale, shift, kern, 64, 64);
  apply2<<<8192, 256>>>(kern, xi, o1, 64, 16, 16, 8, 8, 2097152);

  // ---------------- Layer 2: 64 -> 128, k=2, s=2, p=0, 8x8 -> 4x4 ------------
  gemm_pixel<<<dim3(256, 2), 256>>>(Wi2, o1, xi, 128, 64, 64);
  pool2v<<<2048, 256>>>(o1, xp, 8, 8, 524288);                   // [B,64,4,4]
  gemm_pixel<<<dim3(64, 2), 256>>>(Wr2, xp, r, 128, 64, 16);
  bn_partial<<<dim3(128, 8), 256>>>(r, part, 128, 16, 128);
  bn_finalize<<<1, 256>>>(part, ga2, be2, scale, shift, 128, 8, 1.f / 16384.f);
  span_kernel<4><<<64, 256>>>(Wsp2, r, scale, shift, kern, 128, 16);
  apply2<<<4096, 256>>>(kern, xi, o2, 128, 8, 8, 4, 4, 1048576);

  // ---------------- Layer 3: 128 -> 256, k=3, s=1, p=1, 4x4 -> 4x4 -----------
  gemm_pixel<<<dim3(64, 4), 256>>>(Wi3, o2, xi, 256, 128, 16);
  gemm_pixel<<<dim3(64, 4), 256>>>(Wr3, o2, r, 256, 128, 16);
  bn_partial<<<dim3(256, 8), 256>>>(r, part, 256, 16, 128);
  bn_finalize<<<1, 256>>>(part, ga3, be3, scale, shift, 256, 8, 1.f / 16384.f);
  span_kernel<9><<<64, 256>>>(Wsp3, r, scale, shift, kern, 256, 16);
  apply_kernel<3, 1, 1><<<16384, 256>>>(kern, xi, o3, 256, 4, 4, 4, 4, 4194304);

  // ---------------- FC: [1024,4096] @ [4096,16]^T + bias ---------------------
  fc_kernel<<<64, 256>>>(o3, Wfc, bfc, out);
}